// round 2
// baseline (speedup 1.0000x reference)
#include <cuda_runtime.h>
#include <cstdint>

#define NPROP 36864     // 64*64*9 proposals
#define NTOP  6000      // PRE_NMS_TOPN
#define NW    94        // ceil(6000/64) suppression words per row
#define NOUT  300       // POST_NMS_TOPN
#define NBIN  2048
#define NCAND 8192      // padded pow2 candidate buffer (superset of top-6000)

// ---------------- scratch (device globals; no allocations allowed) ----------
__device__ float4             g_boxes[NPROP];
__device__ unsigned long long g_keys[NPROP];
__device__ unsigned           g_hist[NBIN];
__device__ int                g_ncand;
__device__ int                g_cut;
__device__ unsigned long long g_cand[NCAND];
__device__ float4             g_tbox[NTOP];
__device__ float              g_tarea[NTOP];
__device__ unsigned long long g_validbits[NW];
__device__ unsigned long long g_mask[(size_t)NTOP * NW];   // 4.5 MB

// Anchors for base_size=16, ratios (0.5,1,2) x scales (8,16,32), numpy-round.
__constant__ float c_ax1[9] = {-84.f,-176.f,-360.f,-56.f,-120.f,-248.f,-36.f,-80.f,-168.f};
__constant__ float c_ay1[9] = {-40.f,-88.f,-184.f,-56.f,-120.f,-248.f,-80.f,-168.f,-344.f};
__constant__ float c_aw[9]  = {184.f,368.f,736.f,128.f,256.f,512.f,88.f,176.f,352.f};
__constant__ float c_ah[9]  = {96.f,192.f,384.f,128.f,256.f,512.f,176.f,352.f,704.f};

__device__ __forceinline__ int score_bin(float s) {
    int b = (int)__fmul_rn(s, 2048.0f);
    return b > 2047 ? 2047 : (b < 0 ? 0 : b);
}

// ---------------- 0. init (zero hist, sentinel candidates) -------------------
__global__ void init_kernel() {
    int i = blockIdx.x * blockDim.x + threadIdx.x;
    if (i < NBIN) g_hist[i] = 0;
    if (i < NCAND) g_cand[i] = ~0ULL;
}

// ---------------- 1. decode proposals + keys + histogram ---------------------
__global__ void prop_kernel(const float* __restrict__ scores,
                            const float* __restrict__ deltas) {
    int i = blockIdx.x * blockDim.x + threadIdx.x;
    if (i >= NPROP) return;

    int a   = i % 9;
    int pos = i / 9;                 // pos = h*64 + w
    int wx  = pos % 64;
    int hy  = pos / 64;
    float sx = (float)(wx * 16);
    float sy = (float)(hy * 16);

    const float* d = deltas + (size_t)pos * 36 + a * 4;
    float dx = d[0], dy = d[1], dw = d[2], dh = d[3];
    float score = scores[(size_t)pos * 18 + 9 + a];

    float aw = c_aw[a], ah = c_ah[a];
    float acx = __fadd_rn(__fadd_rn(c_ax1[a], sx), __fmul_rn(0.5f, aw));
    float acy = __fadd_rn(__fadd_rn(c_ay1[a], sy), __fmul_rn(0.5f, ah));

    float pcx = __fadd_rn(__fmul_rn(dx, aw), acx);
    float pcy = __fadd_rn(__fmul_rn(dy, ah), acy);
    float pw  = __fmul_rn(expf(dw), aw);
    float ph  = __fmul_rn(expf(dh), ah);

    float x1 = fminf(fmaxf(__fsub_rn(pcx, __fmul_rn(0.5f, pw)), 0.f), 1023.f);
    float y1 = fminf(fmaxf(__fsub_rn(pcy, __fmul_rn(0.5f, ph)), 0.f), 1023.f);
    float x2 = fminf(fmaxf(__fadd_rn(pcx, __fmul_rn(0.5f, pw)), 0.f), 1023.f);
    float y2 = fminf(fmaxf(__fadd_rn(pcy, __fmul_rn(0.5f, ph)), 0.f), 1023.f);

    float ws = __fadd_rn(__fsub_rn(x2, x1), 1.f);
    float hs = __fadd_rn(__fsub_rn(y2, y1), 1.f);
    bool valid = (ws >= 16.f) && (hs >= 16.f);

    g_boxes[i] = make_float4(x1, y1, x2, y2);

    // key: descending score, ties ascending index (lax.top_k semantics).
    unsigned fk = valid ? (__float_as_uint(score) ^ 0x80000000u) : 0x007FFFFFu;
    g_keys[i] = ((unsigned long long)(~fk) << 32) | (unsigned)i;

    if (valid) atomicAdd(&g_hist[score_bin(score)], 1u);
}

// ---------------- 2. suffix scan over bins -> cutoff bin ---------------------
__global__ void binscan_kernel() {     // 1 block, 1024 threads
    __shared__ unsigned s[NBIN];
    int t = threadIdx.x;
    s[t]        = g_hist[t];
    s[t + 1024] = g_hist[t + 1024];
    __syncthreads();
    for (int d = 1; d < NBIN; d <<= 1) {        // Hillis-Steele suffix sum
        unsigned v0 = (t + d < NBIN)        ? s[t + d]        : 0;
        unsigned v1 = (t + 1024 + d < NBIN) ? s[t + 1024 + d] : 0;
        __syncthreads();
        s[t]        += v0;
        s[t + 1024] += v1;
        __syncthreads();
    }
    unsigned total  = s[0];
    unsigned target = total < NTOP ? total : NTOP;
    // cut = max b with S(b) >= target  (so bins >= cut form the candidate set)
    for (int e = 0; e < 2; e++) {
        int b = t + e * 1024;
        unsigned Sb  = s[b];
        unsigned Sb1 = (b < NBIN - 1) ? s[b + 1] : 0;
        if (Sb >= target && (b == NBIN - 1 || Sb1 < target)) g_cut = b;
    }
    if (t == 0) {
        g_ncand = 0;
        if (total == 0) g_cut = NBIN;   // nothing passes
    }
}

// ---------------- 3. compact candidates --------------------------------------
__global__ void compact_kernel() {
    int i = blockIdx.x * blockDim.x + threadIdx.x;
    if (i >= NPROP) return;
    unsigned long long key = g_keys[i];
    unsigned hk = (unsigned)(key >> 32);
    if (hk == 0xFF800000u) return;                 // invalid (-inf) sentinel
    float score = __uint_as_float(~hk ^ 0x80000000u);
    if (score_bin(score) >= g_cut) {
        int p = atomicAdd(&g_ncand, 1);
        if (p < NCAND) g_cand[p] = key;            // capacity safe: ~6020 << 8192
    }
}

// ---------------- 4. single-block bitonic sort of 8192 keys ------------------
__global__ void sortblk_kernel() {
    extern __shared__ unsigned long long s[];
    int t = threadIdx.x;                 // 1024 threads, 8 elems each
    #pragma unroll
    for (int e = 0; e < 8; e++) s[t + e * 1024] = g_cand[t + e * 1024];
    for (int k = 2; k <= NCAND; k <<= 1) {
        for (int j = k >> 1; j > 0; j >>= 1) {
            __syncthreads();
            #pragma unroll
            for (int e = 0; e < 4; e++) {
                int p  = t + e * 1024;                       // pair 0..4095
                int i1 = ((p & ~(j - 1)) << 1) | (p & (j - 1));
                int i2 = i1 | j;
                bool asc = (i1 & k) == 0;
                unsigned long long a = s[i1], b = s[i2];
                if ((a > b) == asc) { s[i1] = b; s[i2] = a; }
            }
        }
    }
    __syncthreads();
    #pragma unroll
    for (int e = 0; e < 8; e++) g_cand[t + e * 1024] = s[t + e * 1024];
}

// ---------------- 5. gather top-6000 + validity bits -------------------------
__global__ void gather_kernel() {      // grid 94, block 64 (one word per block)
    __shared__ unsigned sb[2];
    int w = blockIdx.x, t = threadIdx.x;
    int i = w * 64 + t;
    bool valid = false;
    float4 b = make_float4(0.f, 0.f, 0.f, 0.f);
    if (i < NTOP) {
        unsigned long long key = g_cand[i];
        unsigned hk = (unsigned)(key >> 32);
        if (hk != 0xFFFFFFFFu) {                   // not the pad sentinel
            b = g_boxes[(unsigned)key];
            valid = true;
        }
    }
    unsigned bal = __ballot_sync(0xFFFFFFFFu, valid);
    if ((t & 31) == 0) sb[t >> 5] = bal;
    __syncthreads();
    if (t == 0) g_validbits[w] = ((unsigned long long)sb[1] << 32) | sb[0];
    if (i < NTOP) {
        g_tbox[i]  = b;
        g_tarea[i] = __fmul_rn(__fadd_rn(__fsub_rn(b.z, b.x), 1.f),
                               __fadd_rn(__fsub_rn(b.w, b.y), 1.f));
    }
}

// ---------------- 6. NMS suppression matrix (upper triangle) -----------------
__global__ void mask_kernel() {
    int rb = blockIdx.x, cb = blockIdx.y;
    if (cb < rb) return;
    __shared__ float4 cbox[64];
    __shared__ float  carea[64];
    int t = threadIdx.x;
    int j0 = cb * 64;
    if (j0 + t < NTOP) { cbox[t] = g_tbox[j0 + t]; carea[t] = g_tarea[j0 + t]; }
    __syncthreads();
    int i = rb * 64 + t;
    if (i >= NTOP) return;
    float4 r = g_tbox[i];
    float  ra = g_tarea[i];
    int jmax = min(64, NTOP - j0);
    unsigned long long bits = 0;
    #pragma unroll 4
    for (int jj = 0; jj < jmax; jj++) {
        int j = j0 + jj;
        if (j <= i) continue;
        float4 c = cbox[jj];
        float xx1 = fmaxf(r.x, c.x);
        float yy1 = fmaxf(r.y, c.y);
        float xx2 = fminf(r.z, c.z);
        float yy2 = fminf(r.w, c.w);
        float iw = fmaxf(__fadd_rn(__fsub_rn(xx2, xx1), 1.f), 0.f);
        float ih = fmaxf(__fadd_rn(__fsub_rn(yy2, yy1), 1.f), 0.f);
        float inter = __fmul_rn(iw, ih);
        float denom = __fsub_rn(__fadd_rn(ra, carea[jj]), inter);
        float iou = __fdiv_rn(inter, denom);
        if (iou > 0.5f) bits |= 1ULL << jj;
    }
    g_mask[(size_t)i * NW + cb] = bits;
}

// ---------------- 7. sequential greedy scan + output -------------------------
__global__ void scan_kernel(float* __restrict__ out) {
    __shared__ unsigned long long remv[NW];
    __shared__ unsigned long long diag[64];
    __shared__ int kept[NOUT];
    __shared__ int cnt;
    __shared__ unsigned long long kwsh;
    int t = threadIdx.x;
    if (t < NW) remv[t] = 0ULL;
    if (t == 0) cnt = 0;
    if (t < 64) diag[t] = (t < NTOP) ? g_mask[(size_t)t * NW + 0] : 0ULL;
    __syncthreads();

    for (int wb = 0; wb < NW; wb++) {
        if (t == 0) {
            unsigned long long r  = remv[wb];
            unsigned long long vw = g_validbits[wb];
            unsigned long long kw = 0;
            int c  = cnt;
            int nb = min(64, NTOP - wb * 64);
            for (int b = 0; b < nb; b++) {
                if (((r >> b) & 1ULL) == 0 && ((vw >> b) & 1ULL)) {
                    kept[c++] = wb * 64 + b;
                    kw |= 1ULL << b;
                    r |= diag[b];
                    if (c == NOUT) break;
                }
            }
            cnt = c;
            kwsh = kw;
        }
        __syncthreads();
        if (cnt >= NOUT || wb == NW - 1) break;

        unsigned long long kw = kwsh;
        for (int w = wb + 1 + t; w < NW; w += blockDim.x) {
            unsigned long long acc = remv[w];
            unsigned long long m = kw;
            while (m) {
                int b = __ffsll((long long)m) - 1;
                m &= m - 1;
                acc |= g_mask[(size_t)(wb * 64 + b) * NW + w];
            }
            remv[w] = acc;
        }
        if (t < 64) {
            int i = (wb + 1) * 64 + t;
            diag[t] = (i < NTOP) ? g_mask[(size_t)i * NW + (wb + 1)] : 0ULL;
        }
        __syncthreads();
    }
    __syncthreads();

    int c = cnt;
    const float inv = 0.0009765625f;   // 1/1024
    for (int o = t; o < NOUT; o += blockDim.x) {
        float4 b = make_float4(0.f, 0.f, 0.f, 0.f);
        if (o < c) {
            float4 bb = g_tbox[kept[o]];
            b.x = bb.x * inv; b.y = bb.y * inv; b.z = bb.z * inv; b.w = bb.w * inv;
        }
        out[o * 4 + 0] = b.x;
        out[o * 4 + 1] = b.y;
        out[o * 4 + 2] = b.z;
        out[o * 4 + 3] = b.w;
    }
}

// ---------------- launch ------------------------------------------------------
extern "C" void kernel_launch(void* const* d_in, const int* in_sizes, int n_in,
                              void* d_out, int out_size) {
    const float* scores = (const float*)d_in[0];
    const float* deltas = (const float*)d_in[1];
    if (in_sizes[0] != 73728) {
        scores = (const float*)d_in[1];
        deltas = (const float*)d_in[0];
    }
    float* out = (float*)d_out;

    static bool attr_set = false;
    if (!attr_set) {
        cudaFuncSetAttribute(sortblk_kernel,
                             cudaFuncAttributeMaxDynamicSharedMemorySize, 65536);
        attr_set = true;
    }

    init_kernel<<<8, 1024>>>();
    prop_kernel<<<(NPROP + 255) / 256, 256>>>(scores, deltas);
    binscan_kernel<<<1, 1024>>>();
    compact_kernel<<<(NPROP + 255) / 256, 256>>>();
    sortblk_kernel<<<1, 1024, 65536>>>();
    gather_kernel<<<NW, 64>>>();
    dim3 mg(NW, NW);
    mask_kernel<<<mg, 64>>>();
    scan_kernel<<<1, 128>>>(out);
}

// round 3
// speedup vs baseline: 1.3309x; 1.3309x over previous
#include <cuda_runtime.h>
#include <cstdint>

#define NPROP 36864     // 64*64*9 proposals
#define NTOP  6000      // PRE_NMS_TOPN
#define NW    94        // ceil(6000/64) suppression words per row
#define NOUT  300       // POST_NMS_TOPN
#define NBIN  2048
#define NCAND 8192      // capacity for candidate superset of top-6000

// ---------------- scratch (device globals; no allocations allowed) ----------
__device__ float4             g_boxes[NPROP];
__device__ unsigned long long g_keys[NPROP];
__device__ unsigned           g_hist[NBIN];
__device__ unsigned           g_binstart[NBIN];
__device__ unsigned           g_binfill[NBIN];
__device__ int                g_ncand;
__device__ int                g_cut;
__device__ unsigned long long g_cand[NCAND];     // bin-grouped, unordered
__device__ unsigned long long g_sorted[NCAND];   // exact descending order
__device__ float4             g_tbox[NTOP];
__device__ float              g_tarea[NTOP];
__device__ unsigned long long g_validbits[NW];
__device__ unsigned long long g_mask[(size_t)NTOP * NW];   // 4.5 MB

// Anchors for base_size=16, ratios (0.5,1,2) x scales (8,16,32), numpy-round.
__constant__ float c_ax1[9] = {-84.f,-176.f,-360.f,-56.f,-120.f,-248.f,-36.f,-80.f,-168.f};
__constant__ float c_ay1[9] = {-40.f,-88.f,-184.f,-56.f,-120.f,-248.f,-80.f,-168.f,-344.f};
__constant__ float c_aw[9]  = {184.f,368.f,736.f,128.f,256.f,512.f,88.f,176.f,352.f};
__constant__ float c_ah[9]  = {96.f,192.f,384.f,128.f,256.f,512.f,176.f,352.f,704.f};

__device__ __forceinline__ int score_bin(float s) {
    int b = (int)__fmul_rn(s, 2048.0f);
    return b > 2047 ? 2047 : (b < 0 ? 0 : b);
}

// ---------------- 0. init ----------------------------------------------------
__global__ void init_kernel() {
    int i = blockIdx.x * blockDim.x + threadIdx.x;
    if (i < NBIN) { g_hist[i] = 0; g_binfill[i] = 0; }
    if (i < NCAND) g_sorted[i] = ~0ULL;           // sentinel => invalid
}

// ---------------- 1. decode proposals + keys + histogram ---------------------
__global__ void prop_kernel(const float* __restrict__ scores,
                            const float* __restrict__ deltas) {
    int i = blockIdx.x * blockDim.x + threadIdx.x;
    if (i >= NPROP) return;

    int a   = i % 9;
    int pos = i / 9;                 // pos = h*64 + w
    int wx  = pos % 64;
    int hy  = pos / 64;
    float sx = (float)(wx * 16);
    float sy = (float)(hy * 16);

    const float* d = deltas + (size_t)pos * 36 + a * 4;
    float dx = d[0], dy = d[1], dw = d[2], dh = d[3];
    float score = scores[(size_t)pos * 18 + 9 + a];

    float aw = c_aw[a], ah = c_ah[a];
    float acx = __fadd_rn(__fadd_rn(c_ax1[a], sx), __fmul_rn(0.5f, aw));
    float acy = __fadd_rn(__fadd_rn(c_ay1[a], sy), __fmul_rn(0.5f, ah));

    float pcx = __fadd_rn(__fmul_rn(dx, aw), acx);
    float pcy = __fadd_rn(__fmul_rn(dy, ah), acy);
    float pw  = __fmul_rn(expf(dw), aw);
    float ph  = __fmul_rn(expf(dh), ah);

    float x1 = fminf(fmaxf(__fsub_rn(pcx, __fmul_rn(0.5f, pw)), 0.f), 1023.f);
    float y1 = fminf(fmaxf(__fsub_rn(pcy, __fmul_rn(0.5f, ph)), 0.f), 1023.f);
    float x2 = fminf(fmaxf(__fadd_rn(pcx, __fmul_rn(0.5f, pw)), 0.f), 1023.f);
    float y2 = fminf(fmaxf(__fadd_rn(pcy, __fmul_rn(0.5f, ph)), 0.f), 1023.f);

    float ws = __fadd_rn(__fsub_rn(x2, x1), 1.f);
    float hs = __fadd_rn(__fsub_rn(y2, y1), 1.f);
    bool valid = (ws >= 16.f) && (hs >= 16.f);

    g_boxes[i] = make_float4(x1, y1, x2, y2);

    // key: ascending key == descending score, ties by ascending index.
    unsigned fk = valid ? (__float_as_uint(score) ^ 0x80000000u) : 0x007FFFFFu;
    g_keys[i] = ((unsigned long long)(~fk) << 32) | (unsigned)i;

    if (valid) atomicAdd(&g_hist[score_bin(score)], 1u);
}

// ---------------- 2. suffix scan over bins -> cutoff + bin starts ------------
__global__ void binscan_kernel() {     // 1 block, 1024 threads
    __shared__ unsigned s[NBIN];
    int t = threadIdx.x;
    unsigned h0 = g_hist[t], h1 = g_hist[t + 1024];
    s[t] = h0; s[t + 1024] = h1;
    __syncthreads();
    for (int d = 1; d < NBIN; d <<= 1) {        // Hillis-Steele suffix sum
        unsigned v0 = (t + d < NBIN)        ? s[t + d]        : 0;
        unsigned v1 = (t + 1024 + d < NBIN) ? s[t + 1024 + d] : 0;
        __syncthreads();
        s[t]        += v0;
        s[t + 1024] += v1;
        __syncthreads();
    }
    // binstart[b] = S(b) - hist[b] = count of keys in bins > b
    g_binstart[t]        = s[t] - h0;
    g_binstart[t + 1024] = s[t + 1024] - h1;
    unsigned total  = s[0];
    unsigned target = total < NTOP ? total : NTOP;
    for (int e = 0; e < 2; e++) {
        int b = t + e * 1024;
        unsigned Sb  = s[b];
        unsigned Sb1 = (b < NBIN - 1) ? s[b + 1] : 0;
        if (Sb >= target && (b == NBIN - 1 || Sb1 < target)) {
            g_cut = b;
            g_ncand = (int)(Sb < NCAND ? Sb : NCAND);
        }
    }
    if (t == 0 && total == 0) { g_cut = NBIN; g_ncand = 0; }
}

// ---------------- 3. scatter candidates into bin-grouped segments ------------
__global__ void scatter_kernel() {
    int i = blockIdx.x * blockDim.x + threadIdx.x;
    if (i >= NPROP) return;
    unsigned long long key = g_keys[i];
    unsigned hk = (unsigned)(key >> 32);
    if (hk == 0xFF800000u) return;                 // invalid (-inf)
    float score = __uint_as_float(~hk ^ 0x80000000u);
    int b = score_bin(score);
    if (b < g_cut) return;
    unsigned pos = g_binstart[b] + atomicAdd(&g_binfill[b], 1u);
    if (pos < NCAND) g_cand[pos] = key;
}

// ---------------- 4. exact rank within bin -> scatter to sorted order --------
__global__ void rank_kernel() {
    int p = blockIdx.x * blockDim.x + threadIdx.x;
    if (p >= g_ncand) return;
    unsigned long long key = g_cand[p];
    unsigned hk = (unsigned)(key >> 32);
    float score = __uint_as_float(~hk ^ 0x80000000u);
    int b = score_bin(score);
    unsigned seg0 = g_binstart[b];
    unsigned segn = g_hist[b];
    if (seg0 + segn > NCAND) segn = NCAND - seg0;
    unsigned r = 0;
    for (unsigned q = 0; q < segn; q++)
        r += (g_cand[seg0 + q] < key) ? 1u : 0u;   // keys unique (idx in low32)
    unsigned rank = seg0 + r;
    if (rank < NCAND) g_sorted[rank] = key;
}

// ---------------- 5. gather top-6000 + validity bits -------------------------
__global__ void gather_kernel() {      // grid 94, block 64 (one word per block)
    __shared__ unsigned sb[2];
    int w = blockIdx.x, t = threadIdx.x;
    int i = w * 64 + t;
    bool valid = false;
    float4 b = make_float4(0.f, 0.f, 0.f, 0.f);
    if (i < NTOP) {
        unsigned long long key = g_sorted[i];
        unsigned hk = (unsigned)(key >> 32);
        if (hk != 0xFFFFFFFFu) {                   // not the pad sentinel
            b = g_boxes[(unsigned)key];
            valid = true;
        }
    }
    unsigned bal = __ballot_sync(0xFFFFFFFFu, valid);
    if ((t & 31) == 0) sb[t >> 5] = bal;
    __syncthreads();
    if (t == 0) g_validbits[w] = ((unsigned long long)sb[1] << 32) | sb[0];
    if (i < NTOP) {
        g_tbox[i]  = b;
        g_tarea[i] = __fmul_rn(__fadd_rn(__fsub_rn(b.z, b.x), 1.f),
                               __fadd_rn(__fsub_rn(b.w, b.y), 1.f));
    }
}

// ---------------- 6. NMS suppression matrix (upper triangle) -----------------
__global__ void mask_kernel() {
    int rb = blockIdx.x, cb = blockIdx.y;
    if (cb < rb) return;
    __shared__ float4 cbox[64];
    __shared__ float  carea[64];
    int t = threadIdx.x;
    int j0 = cb * 64;
    if (j0 + t < NTOP) { cbox[t] = g_tbox[j0 + t]; carea[t] = g_tarea[j0 + t]; }
    __syncthreads();
    int i = rb * 64 + t;
    if (i >= NTOP) return;
    float4 r = g_tbox[i];
    float  ra = g_tarea[i];
    int jmax = min(64, NTOP - j0);
    unsigned long long bits = 0;
    #pragma unroll 4
    for (int jj = 0; jj < jmax; jj++) {
        int j = j0 + jj;
        if (j <= i) continue;
        float4 c = cbox[jj];
        float xx1 = fmaxf(r.x, c.x);
        float yy1 = fmaxf(r.y, c.y);
        float xx2 = fminf(r.z, c.z);
        float yy2 = fminf(r.w, c.w);
        float iw = fmaxf(__fadd_rn(__fsub_rn(xx2, xx1), 1.f), 0.f);
        float ih = fmaxf(__fadd_rn(__fsub_rn(yy2, yy1), 1.f), 0.f);
        float inter = __fmul_rn(iw, ih);
        float denom = __fsub_rn(__fadd_rn(ra, carea[jj]), inter);
        float iou = __fdiv_rn(inter, denom);
        if (iou > 0.5f) bits |= 1ULL << jj;
    }
    g_mask[(size_t)i * NW + cb] = bits;
}

// ---------------- 7. sequential greedy scan + output -------------------------
__global__ void scan_kernel(float* __restrict__ out) {
    __shared__ unsigned long long remv[NW];
    __shared__ unsigned long long diag[64];
    __shared__ int kept[NOUT];
    __shared__ int cnt;
    __shared__ unsigned long long kwsh;
    int t = threadIdx.x;
    if (t < NW) remv[t] = 0ULL;
    if (t == 0) cnt = 0;
    if (t < 64) diag[t] = (t < NTOP) ? g_mask[(size_t)t * NW + 0] : 0ULL;
    __syncthreads();

    for (int wb = 0; wb < NW; wb++) {
        if (t == 0) {
            unsigned long long r  = remv[wb];
            unsigned long long vw = g_validbits[wb];
            unsigned long long kw = 0;
            int c  = cnt;
            int nb = min(64, NTOP - wb * 64);
            for (int b = 0; b < nb; b++) {
                if (((r >> b) & 1ULL) == 0 && ((vw >> b) & 1ULL)) {
                    kept[c++] = wb * 64 + b;
                    kw |= 1ULL << b;
                    r |= diag[b];
                    if (c == NOUT) break;
                }
            }
            cnt = c;
            kwsh = kw;
        }
        __syncthreads();
        if (cnt >= NOUT || wb == NW - 1) break;

        unsigned long long kw = kwsh;
        for (int w = wb + 1 + t; w < NW; w += blockDim.x) {
            unsigned long long acc = remv[w];
            unsigned long long m = kw;
            while (m) {
                int b = __ffsll((long long)m) - 1;
                m &= m - 1;
                acc |= g_mask[(size_t)(wb * 64 + b) * NW + w];
            }
            remv[w] = acc;
        }
        if (t < 64) {
            int i = (wb + 1) * 64 + t;
            diag[t] = (i < NTOP) ? g_mask[(size_t)i * NW + (wb + 1)] : 0ULL;
        }
        __syncthreads();
    }
    __syncthreads();

    int c = cnt;
    const float inv = 0.0009765625f;   // 1/1024
    for (int o = t; o < NOUT; o += blockDim.x) {
        float4 b = make_float4(0.f, 0.f, 0.f, 0.f);
        if (o < c) {
            float4 bb = g_tbox[kept[o]];
            b.x = bb.x * inv; b.y = bb.y * inv; b.z = bb.z * inv; b.w = bb.w * inv;
        }
        out[o * 4 + 0] = b.x;
        out[o * 4 + 1] = b.y;
        out[o * 4 + 2] = b.z;
        out[o * 4 + 3] = b.w;
    }
}

// ---------------- launch ------------------------------------------------------
extern "C" void kernel_launch(void* const* d_in, const int* in_sizes, int n_in,
                              void* d_out, int out_size) {
    const float* scores = (const float*)d_in[0];
    const float* deltas = (const float*)d_in[1];
    if (in_sizes[0] != 73728) {
        scores = (const float*)d_in[1];
        deltas = (const float*)d_in[0];
    }
    float* out = (float*)d_out;

    init_kernel<<<8, 1024>>>();
    prop_kernel<<<(NPROP + 255) / 256, 256>>>(scores, deltas);
    binscan_kernel<<<1, 1024>>>();
    scatter_kernel<<<(NPROP + 255) / 256, 256>>>();
    rank_kernel<<<NCAND / 256, 256>>>();
    gather_kernel<<<NW, 64>>>();
    dim3 mg(NW, NW);
    mask_kernel<<<mg, 64>>>();
    scan_kernel<<<1, 128>>>(out);
}

// round 4
// speedup vs baseline: 1.4625x; 1.0989x over previous
#include <cuda_runtime.h>
#include <cstdint>

#define NPROP 36864     // 64*64*9 proposals
#define NTOP  6000      // PRE_NMS_TOPN
#define NW    94        // ceil(6000/64) suppression words per row
#define NOUT  300       // POST_NMS_TOPN
#define NBIN  2048
#define NCAND 8192      // capacity for candidate superset of top-6000

// ---------------- scratch (device globals; no allocations allowed) ----------
__device__ float4             g_boxes[NPROP];
__device__ unsigned long long g_keys[NPROP];
__device__ unsigned           g_hist[NBIN];
__device__ unsigned           g_binstart[NBIN];
__device__ int                g_ncand;
__device__ unsigned long long g_cand[NCAND];     // bin-grouped, unordered
__device__ unsigned long long g_sorted[NCAND];   // exact descending order
__device__ float4             g_tbox[NTOP];
__device__ float              g_tarea[NTOP];
__device__ unsigned long long g_validbits[NW];
__device__ unsigned long long g_mask[(size_t)NTOP * NW];   // 4.5 MB

// Anchors for base_size=16, ratios (0.5,1,2) x scales (8,16,32), numpy-round.
__constant__ float c_ax1[9] = {-84.f,-176.f,-360.f,-56.f,-120.f,-248.f,-36.f,-80.f,-168.f};
__constant__ float c_ay1[9] = {-40.f,-88.f,-184.f,-56.f,-120.f,-248.f,-80.f,-168.f,-344.f};
__constant__ float c_aw[9]  = {184.f,368.f,736.f,128.f,256.f,512.f,88.f,176.f,352.f};
__constant__ float c_ah[9]  = {96.f,192.f,384.f,128.f,256.f,512.f,176.f,352.f,704.f};

__device__ __forceinline__ int score_bin(float s) {
    int b = (int)__fmul_rn(s, 2048.0f);
    return b > 2047 ? 2047 : (b < 0 ? 0 : b);
}

// ---------------- 0. init ----------------------------------------------------
__global__ void init_kernel() {
    int i = blockIdx.x * blockDim.x + threadIdx.x;
    if (i < NBIN) g_hist[i] = 0;
    if (i < NCAND) g_sorted[i] = ~0ULL;           // sentinel => invalid
}

// ---------------- 1. decode proposals + keys + histogram ---------------------
__global__ void prop_kernel(const float* __restrict__ scores,
                            const float* __restrict__ deltas) {
    int i = blockIdx.x * blockDim.x + threadIdx.x;
    if (i >= NPROP) return;

    int a   = i % 9;
    int pos = i / 9;                 // pos = h*64 + w
    int wx  = pos % 64;
    int hy  = pos / 64;
    float sx = (float)(wx * 16);
    float sy = (float)(hy * 16);

    const float* d = deltas + (size_t)pos * 36 + a * 4;
    float dx = d[0], dy = d[1], dw = d[2], dh = d[3];
    float score = scores[(size_t)pos * 18 + 9 + a];

    float aw = c_aw[a], ah = c_ah[a];
    float acx = __fadd_rn(__fadd_rn(c_ax1[a], sx), __fmul_rn(0.5f, aw));
    float acy = __fadd_rn(__fadd_rn(c_ay1[a], sy), __fmul_rn(0.5f, ah));

    float pcx = __fadd_rn(__fmul_rn(dx, aw), acx);
    float pcy = __fadd_rn(__fmul_rn(dy, ah), acy);
    float pw  = __fmul_rn(expf(dw), aw);
    float ph  = __fmul_rn(expf(dh), ah);

    float x1 = fminf(fmaxf(__fsub_rn(pcx, __fmul_rn(0.5f, pw)), 0.f), 1023.f);
    float y1 = fminf(fmaxf(__fsub_rn(pcy, __fmul_rn(0.5f, ph)), 0.f), 1023.f);
    float x2 = fminf(fmaxf(__fadd_rn(pcx, __fmul_rn(0.5f, pw)), 0.f), 1023.f);
    float y2 = fminf(fmaxf(__fadd_rn(pcy, __fmul_rn(0.5f, ph)), 0.f), 1023.f);

    float ws = __fadd_rn(__fsub_rn(x2, x1), 1.f);
    float hs = __fadd_rn(__fsub_rn(y2, y1), 1.f);
    bool valid = (ws >= 16.f) && (hs >= 16.f);

    g_boxes[i] = make_float4(x1, y1, x2, y2);

    // key: ascending key == descending score, ties by ascending index.
    unsigned fk = valid ? (__float_as_uint(score) ^ 0x80000000u) : 0x007FFFFFu;
    g_keys[i] = ((unsigned long long)(~fk) << 32) | (unsigned)i;

    if (valid) atomicAdd(&g_hist[score_bin(score)], 1u);
}

// ---------------- 2. suffix scan + cutoff + scatter (one block) --------------
__global__ void select_kernel() {      // 1 block, 1024 threads
    __shared__ unsigned s[NBIN];
    __shared__ unsigned fill[NBIN];
    __shared__ int scut;
    int t = threadIdx.x;
    unsigned h0 = g_hist[t], h1 = g_hist[t + 1024];
    s[t] = h0; s[t + 1024] = h1;
    fill[t] = 0; fill[t + 1024] = 0;
    __syncthreads();
    for (int d = 1; d < NBIN; d <<= 1) {        // Hillis-Steele suffix sum
        unsigned v0 = (t + d < NBIN)        ? s[t + d]        : 0;
        unsigned v1 = (t + 1024 + d < NBIN) ? s[t + 1024 + d] : 0;
        __syncthreads();
        s[t]        += v0;
        s[t + 1024] += v1;
        __syncthreads();
    }
    // binstart[b] = S(b) - hist[b] = count of keys in bins > b
    g_binstart[t]        = s[t] - h0;
    g_binstart[t + 1024] = s[t + 1024] - h1;
    unsigned total  = s[0];
    unsigned target = total < NTOP ? total : NTOP;
    for (int e = 0; e < 2; e++) {
        int b = t + e * 1024;
        unsigned Sb  = s[b];
        unsigned Sb1 = (b < NBIN - 1) ? s[b + 1] : 0;
        if (Sb >= target && (b == NBIN - 1 || Sb1 < target)) {
            scut = b;
            g_ncand = (int)(Sb < NCAND ? Sb : NCAND);
        }
    }
    if (t == 0 && total == 0) { scut = NBIN; g_ncand = 0; }
    __syncthreads();
    int cut = scut;
    // scatter: each thread walks 36 keys
    for (int i = t; i < NPROP; i += 1024) {
        unsigned long long key = g_keys[i];
        unsigned hk = (unsigned)(key >> 32);
        if (hk == 0xFF800000u) continue;           // invalid (-inf)
        float score = __uint_as_float(~hk ^ 0x80000000u);
        int b = score_bin(score);
        if (b < cut) continue;
        unsigned pos = (s[b] - g_hist[b]) + atomicAdd(&fill[b], 1u);
        if (pos < NCAND) g_cand[pos] = key;
    }
}

// ---------------- 3. exact rank within bin -> scatter to sorted order --------
__global__ void rank_kernel() {
    int p = blockIdx.x * blockDim.x + threadIdx.x;
    if (p >= g_ncand) return;
    unsigned long long key = g_cand[p];
    unsigned hk = (unsigned)(key >> 32);
    float score = __uint_as_float(~hk ^ 0x80000000u);
    int b = score_bin(score);
    unsigned seg0 = g_binstart[b];
    unsigned segn = g_hist[b];
    if (seg0 + segn > NCAND) segn = NCAND - seg0;
    unsigned r = 0;
    for (unsigned q = 0; q < segn; q++)
        r += (g_cand[seg0 + q] < key) ? 1u : 0u;   // keys unique (idx in low32)
    unsigned rank = seg0 + r;
    if (rank < NCAND) g_sorted[rank] = key;
}

// ---------------- 4. gather top-6000 + validity bits -------------------------
__global__ void gather_kernel() {      // grid 94, block 64
    __shared__ unsigned sb[2];
    int w = blockIdx.x, t = threadIdx.x;
    int i = w * 64 + t;
    bool valid = false;
    float4 b = make_float4(0.f, 0.f, 0.f, 0.f);
    if (i < NTOP) {
        unsigned long long key = g_sorted[i];
        unsigned hk = (unsigned)(key >> 32);
        if (hk != 0xFFFFFFFFu) {                   // not the pad sentinel
            b = g_boxes[(unsigned)key];
            valid = true;
        }
    }
    unsigned bal = __ballot_sync(0xFFFFFFFFu, valid);
    if ((t & 31) == 0) sb[t >> 5] = bal;
    __syncthreads();
    if (t == 0) g_validbits[w] = ((unsigned long long)sb[1] << 32) | sb[0];
    if (i < NTOP) {
        g_tbox[i]  = b;
        g_tarea[i] = __fmul_rn(__fadd_rn(__fsub_rn(b.z, b.x), 1.f),
                               __fadd_rn(__fsub_rn(b.w, b.y), 1.f));
    }
}

// ---------------- 5. NMS suppression matrix (upper triangle, div-free) -------
__global__ void mask_kernel() {
    int rb = blockIdx.x, cb = blockIdx.y;
    if (cb < rb) return;
    __shared__ float4 cbox[64];
    __shared__ float  carea[64];
    int t = threadIdx.x;
    int j0 = cb * 64;
    if (j0 + t < NTOP) { cbox[t] = g_tbox[j0 + t]; carea[t] = g_tarea[j0 + t]; }
    __syncthreads();
    int i = rb * 64 + t;
    if (i >= NTOP) return;
    float4 r = g_tbox[i];
    float  ra = g_tarea[i];
    int jmax = min(64, NTOP - j0);
    unsigned long long bits = 0;
    #pragma unroll 4
    for (int jj = 0; jj < jmax; jj++) {
        int j = j0 + jj;
        if (j <= i) continue;
        float4 c = cbox[jj];
        float xx1 = fmaxf(r.x, c.x);
        float yy1 = fmaxf(r.y, c.y);
        float xx2 = fminf(r.z, c.z);
        float yy2 = fminf(r.w, c.w);
        float iw = fmaxf(__fadd_rn(__fsub_rn(xx2, xx1), 1.f), 0.f);
        float ih = fmaxf(__fadd_rn(__fsub_rn(yy2, yy1), 1.f), 0.f);
        float inter = __fmul_rn(iw, ih);
        float denom = __fsub_rn(__fadd_rn(ra, carea[jj]), inter);
        // iou > 0.5  <=>  inter > 0.5*denom  (0.5*denom exact; denom > 0)
        if (inter > __fmul_rn(0.5f, denom)) bits |= 1ULL << jj;
    }
    g_mask[(size_t)i * NW + cb] = bits;
}

// ---------------- 6. sequential greedy scan + output -------------------------
__global__ void scan_kernel(float* __restrict__ out) {
    __shared__ unsigned long long remv[NW];
    __shared__ unsigned long long diag[64];
    __shared__ int kept[NOUT];
    __shared__ int cnt;
    __shared__ unsigned long long kwsh;
    int t = threadIdx.x;
    if (t < NW) remv[t] = 0ULL;
    if (t == 0) cnt = 0;
    if (t < 64) diag[t] = (t < NTOP) ? g_mask[(size_t)t * NW + 0] : 0ULL;
    __syncthreads();

    for (int wb = 0; wb < NW; wb++) {
        if (t == 0) {   // bit-skipping serial pass: iterations == keeps in word
            unsigned long long avail = ~remv[wb] & g_validbits[wb];
            unsigned long long kw = 0;
            int c = cnt;
            while (avail) {
                int b = __ffsll((long long)avail) - 1;
                kept[c++] = wb * 64 + b;
                kw |= 1ULL << b;
                if (c == NOUT) break;               // later keeps can't matter
                avail &= ~((1ULL << b) | diag[b]);  // self + in-word suppression
            }
            cnt = c;
            kwsh = kw;
        }
        __syncthreads();
        if (cnt >= NOUT || wb == NW - 1) break;

        unsigned long long kw = kwsh;
        for (int w = wb + 1 + t; w < NW; w += blockDim.x) {
            unsigned long long acc = remv[w];
            unsigned long long m = kw;
            while (m) {
                int b = __ffsll((long long)m) - 1;
                m &= m - 1;
                acc |= g_mask[(size_t)(wb * 64 + b) * NW + w];
            }
            remv[w] = acc;
        }
        if (t < 64) {
            int i = (wb + 1) * 64 + t;
            diag[t] = (i < NTOP) ? g_mask[(size_t)i * NW + (wb + 1)] : 0ULL;
        }
        __syncthreads();
    }
    __syncthreads();

    int c = cnt;
    const float inv = 0.0009765625f;   // 1/1024
    for (int o = t; o < NOUT; o += blockDim.x) {
        float4 b = make_float4(0.f, 0.f, 0.f, 0.f);
        if (o < c) {
            float4 bb = g_tbox[kept[o]];
            b.x = bb.x * inv; b.y = bb.y * inv; b.z = bb.z * inv; b.w = bb.w * inv;
        }
        out[o * 4 + 0] = b.x;
        out[o * 4 + 1] = b.y;
        out[o * 4 + 2] = b.z;
        out[o * 4 + 3] = b.w;
    }
}

// ---------------- launch ------------------------------------------------------
extern "C" void kernel_launch(void* const* d_in, const int* in_sizes, int n_in,
                              void* d_out, int out_size) {
    const float* scores = (const float*)d_in[0];
    const float* deltas = (const float*)d_in[1];
    if (in_sizes[0] != 73728) {
        scores = (const float*)d_in[1];
        deltas = (const float*)d_in[0];
    }
    float* out = (float*)d_out;

    init_kernel<<<8, 1024>>>();
    prop_kernel<<<(NPROP + 255) / 256, 256>>>(scores, deltas);
    select_kernel<<<1, 1024>>>();
    rank_kernel<<<NCAND / 256, 256>>>();
    gather_kernel<<<NW, 64>>>();
    dim3 mg(NW, NW);
    mask_kernel<<<mg, 64>>>();
    scan_kernel<<<1, 128>>>(out);
}